// round 15
// baseline (speedup 1.0000x reference)
#include <cuda_runtime.h>
#include <cuda_fp16.h>
#include <math.h>
#include <stdint.h>

#define SEQ 8192
#define IN_DIM 1024
#define HID 2048
#define NEXP 8
#define TOPK 2
#define NTOK (SEQ * TOPK)
#define BM 128
#define BK 64
#define PERM_MAX (NTOK + NEXP * BM)  // 17408

// smem rows padded to 72 fp16 (144B): 8-row ldmatrix tiles hit disjoint bank groups
#define LDK 72
#define ROW_B (LDK * 2)              // 144 bytes per row

// GEMM1 stage: A(128) U(64) G(64) rows
#define S1_AH 0
#define S1_UH (128 * ROW_B)          // 18432
#define S1_GH (192 * ROW_B)          // 27648
#define STG1  (256 * ROW_B)          // 36864
// GEMM2 stage: A(128) B(128) rows
#define S2_AH 0
#define S2_BH (128 * ROW_B)
#define STG2  (256 * ROW_B)          // 36864
#define NSTAGE 3
#define SMEM1 (NSTAGE * STG1)        // 110592 (x2 CTAs = 221184 < 228KB)
#define SMEM2 (NSTAGE * STG2)        // 110592

// ---------------- static device scratch ----------------
__device__ int g_count[NEXP];
__device__ int g_fill[NEXP];
__device__ int g_pbase[NEXP + 1];
__device__ int g_perm[PERM_MAX];

__device__ __half g_up[(size_t)NEXP * HID * IN_DIM];
__device__ __half g_gt[(size_t)NEXP * HID * IN_DIM];
__device__ __half g_dn[(size_t)NEXP * IN_DIM * HID];   // transposed [e][n][k]
__device__ __half g_in[(size_t)SEQ * IN_DIM];
__device__ __half g_act[(size_t)PERM_MAX * HID];
__device__ float g_y[(size_t)NTOK * IN_DIM];

// ---------------- helpers ----------------
__device__ __forceinline__ uint32_t smem_u32(const void* p) {
    uint32_t a;
    asm("{ .reg .u64 t; cvta.to.shared.u64 t, %1; cvt.u32.u64 %0, t; }" : "=r"(a) : "l"(p));
    return a;
}
__device__ __forceinline__ void cp16(uint32_t dst, const void* src, int sz) {
    asm volatile("cp.async.cg.shared.global [%0], [%1], 16, %2;" :: "r"(dst), "l"(src), "r"(sz) : "memory");
}
__device__ __forceinline__ void cp_commit() { asm volatile("cp.async.commit_group;" ::: "memory"); }
__device__ __forceinline__ void cp_wait1() { asm volatile("cp.async.wait_group 1;" ::: "memory"); }

__device__ __forceinline__ void ldm4(uint32_t* r, uint32_t a) {
    asm volatile("ldmatrix.sync.aligned.m8n8.x4.shared.b16 {%0,%1,%2,%3},[%4];"
                 : "=r"(r[0]), "=r"(r[1]), "=r"(r[2]), "=r"(r[3]) : "r"(a));
}
__device__ __forceinline__ void mma16816(float* c, const uint32_t* a, const uint32_t* b) {
    asm volatile("mma.sync.aligned.m16n8k16.row.col.f32.f16.f16.f32 "
                 "{%0,%1,%2,%3},{%4,%5,%6,%7},{%8,%9},{%0,%1,%2,%3};"
                 : "+f"(c[0]), "+f"(c[1]), "+f"(c[2]), "+f"(c[3])
                 : "r"(a[0]), "r"(a[1]), "r"(a[2]), "r"(a[3]), "r"(b[0]), "r"(b[1]));
}
__device__ __forceinline__ float fast_tanh(float x) {
    float y;
    asm("tanh.approx.f32 %0, %1;" : "=f"(y) : "f"(x));
    return y;
}
__device__ __forceinline__ float gelu_tanh(float x) {
    float x3 = x * x * x;
    return 0.5f * x * (1.f + fast_tanh(0.7978845608028654f * (x + 0.044715f * x3)));
}

// ---------------- routing ----------------
__global__ void k_init() {
    int i = blockIdx.x * blockDim.x + threadIdx.x;
    if (i < NEXP) { g_count[i] = 0; g_fill[i] = 0; }
    for (int j = i; j < PERM_MAX; j += gridDim.x * blockDim.x) g_perm[j] = -1;
}
__global__ void k_count(const int* __restrict__ sel) {
    int s = blockIdx.x * blockDim.x + threadIdx.x;
    if (s < NTOK) atomicAdd(&g_count[sel[s]], 1);
}
__global__ void k_scan() {
    if (threadIdx.x == 0) {
        int acc = 0;
        g_pbase[0] = 0;
        for (int e = 0; e < NEXP; e++) {
            acc += ((g_count[e] + BM - 1) / BM) * BM;
            g_pbase[e + 1] = acc;
        }
    }
}
__global__ void k_scatter(const int* __restrict__ sel) {
    int s = blockIdx.x * blockDim.x + threadIdx.x;
    if (s < NTOK) {
        int e = sel[s];
        int pos = g_pbase[e] + atomicAdd(&g_fill[e], 1);
        g_perm[pos] = s;
    }
}

// ---------------- conversions ----------------
__global__ void k_cvt_w(const float* __restrict__ src, int n4, int which) {
    __half* dst = (which == 0) ? g_up : ((which == 1) ? g_gt : g_in);
    for (int i = blockIdx.x * blockDim.x + threadIdx.x; i < n4; i += gridDim.x * blockDim.x) {
        float4 v = ((const float4*)src)[i];
        __half2* D = (__half2*)dst + 2 * (size_t)i;
        D[0] = __halves2half2(__float2half_rn(v.x), __float2half_rn(v.y));
        D[1] = __halves2half2(__float2half_rn(v.z), __float2half_rn(v.w));
    }
}
// down [e][k(HID)][n(IN_DIM)] -> g_dn [e][n][k] fp16, vectorized transpose
// tile: 32 n-cols x 64 k-rows; blockDim (32,8)
__global__ void k_cvt_dnT(const float* __restrict__ down) {
    __shared__ float t[32][65];   // t[n][k]
    int tx = threadIdx.x, ty = threadIdx.y;
    int e = blockIdx.z;
    int n0 = blockIdx.x * 32, k0 = blockIdx.y * 64;
    #pragma unroll
    for (int kr = ty; kr < 64; kr += 8)       // coalesced 128B reads
        t[tx][kr] = down[((size_t)e * HID + k0 + kr) * IN_DIM + n0 + tx];
    __syncthreads();
    #pragma unroll
    for (int nr = ty; nr < 32; nr += 8) {     // half2 rows: 128B per warp store
        float a = t[nr][2 * tx], b = t[nr][2 * tx + 1];
        __half2 h = __halves2half2(__float2half_rn(a), __float2half_rn(b));
        *(__half2*)&g_dn[((size_t)e * IN_DIM + n0 + nr) * HID + k0 + 2 * tx] = h;
    }
}

// ---------------- GEMM1 fused (BM=128, BN=64, BK=64, occ 2): epilogue gelu*h -> act fp16 ----------------
__global__ __launch_bounds__(256, 2) void k_gemm1() {
    int row0 = blockIdx.x * BM;
    if (row0 >= g_pbase[NEXP]) return;
    int nblk = blockIdx.y;

    extern __shared__ char sm[];
    __shared__ int s_tok[BM];
    int tid = threadIdx.x, lane = tid & 31, wid = tid >> 5;

    int e = 0;
    while (row0 >= g_pbase[e + 1]) e++;
    if (tid < BM) {
        int s = g_perm[row0 + tid];
        s_tok[tid] = (s >= 0) ? (s >> 1) : -1;
    }
    __syncthreads();

    size_t wof = ((size_t)e * HID + (size_t)nblk * 64) * IN_DIM;
    const __half* U = g_up + wof;
    const __half* G = g_gt + wof;
    uint32_t sb = smem_u32(sm);

    auto load_stage = [&](int st, int k0) {
        uint32_t base = sb + (uint32_t)st * STG1;
        #pragma unroll
        for (int i = 0; i < 4; i++) {           // A: 128 rows x 8 chunks = 1024 cp
            int idx = tid + i * 256;
            int r = idx >> 3, c = idx & 7;
            uint32_t d = base + S1_AH + (uint32_t)(r * LDK + c * 8) * 2;
            int tok = s_tok[r];
            size_t ao = (size_t)(tok < 0 ? 0 : tok) * IN_DIM + k0 + c * 8;
            cp16(d, g_in + ao, tok < 0 ? 0 : 16);
        }
        #pragma unroll
        for (int i = 0; i < 4; i++) {           // U/G: 64 rows x 8 chunks x 2 = 1024 cp
            int idx = tid + i * 256;
            int r = idx >> 4, wsel = (idx >> 3) & 1, c = idx & 7;
            uint32_t d = base + (wsel ? S1_GH : S1_UH) + (uint32_t)(r * LDK + c * 8) * 2;
            size_t so = (size_t)r * IN_DIM + k0 + c * 8;
            cp16(d, (wsel ? G : U) + so, 16);
        }
        cp_commit();
    };

    int wm = (wid >> 1) * 32, wn = (wid & 1) * 32;
    float acc_u[2][4][4], acc_g[2][4][4];
    #pragma unroll
    for (int a = 0; a < 2; a++)
        #pragma unroll
        for (int b = 0; b < 4; b++)
            #pragma unroll
            for (int c = 0; c < 4; c++) { acc_u[a][b][c] = 0.f; acc_g[a][b][c] = 0.f; }

    load_stage(0, 0);
    load_stage(1, BK);

    const int NS = IN_DIM / BK;  // 16
    for (int s = 0; s < NS; s++) {
        cp_wait1();
        __syncthreads();
        if (s + 2 < NS) load_stage((s + 2) % NSTAGE, (s + 2) * BK);
        else cp_commit();

        uint32_t base = sb + (uint32_t)(s % NSTAGE) * STG1;
        #pragma unroll
        for (int kh = 0; kh < 4; kh++) {
            uint32_t ah[2][4];
            #pragma unroll
            for (int mt = 0; mt < 2; mt++) {
                uint32_t arow = wm + mt * 16 + (lane & 15);
                uint32_t acol = kh * 16 + 8 * (lane >> 4);
                uint32_t off = (arow * LDK + acol) * 2;
                ldm4(ah[mt], base + S1_AH + off);
            }
            uint32_t ub[4][2], gb[4][2];
            #pragma unroll
            for (int p = 0; p < 2; p++) {
                uint32_t quad = (uint32_t)(lane >> 3);
                uint32_t brow = wn + p * 16 + (quad >> 1) * 8 + (lane & 7);
                uint32_t bcol = kh * 16 + (quad & 1) * 8;
                uint32_t off = (brow * LDK + bcol) * 2;
                uint32_t t[4];
                ldm4(t, base + S1_UH + off);
                ub[2*p][0]=t[0]; ub[2*p][1]=t[1]; ub[2*p+1][0]=t[2]; ub[2*p+1][1]=t[3];
                ldm4(t, base + S1_GH + off);
                gb[2*p][0]=t[0]; gb[2*p][1]=t[1]; gb[2*p+1][0]=t[2]; gb[2*p+1][1]=t[3];
            }
            #pragma unroll
            for (int mt = 0; mt < 2; mt++)
                #pragma unroll
                for (int nt = 0; nt < 4; nt++) mma16816(acc_u[mt][nt], ah[mt], ub[nt]);
            #pragma unroll
            for (int mt = 0; mt < 2; mt++)
                #pragma unroll
                for (int nt = 0; nt < 4; nt++) mma16816(acc_g[mt][nt], ah[mt], gb[nt]);
        }
    }

    // epilogue: act = gelu(g) * h -> fp16
    #pragma unroll
    for (int mt = 0; mt < 2; mt++) {
        int gr = row0 + wm + mt * 16 + (lane >> 2);
        #pragma unroll
        for (int nt = 0; nt < 4; nt++) {
            int gc = nblk * 64 + wn + nt * 8 + (lane & 3) * 2;
            #pragma unroll
            for (int half = 0; half < 2; half++) {
                float a0 = gelu_tanh(acc_g[mt][nt][2 * half])     * acc_u[mt][nt][2 * half];
                float a1 = gelu_tanh(acc_g[mt][nt][2 * half + 1]) * acc_u[mt][nt][2 * half + 1];
                __half2 hp = __halves2half2(__float2half_rn(a0), __float2half_rn(a1));
                size_t o = (size_t)(gr + 8 * half) * HID + gc;
                *(uint32_t*)&g_act[o] = *(uint32_t*)&hp;
            }
        }
    }
}

// ---------------- GEMM2 (BM=128, BN=128, BK=64, occ 2): act @ downT ----------------
__global__ __launch_bounds__(256, 2) void k_gemm2() {
    int row0 = blockIdx.x * BM;
    if (row0 >= g_pbase[NEXP]) return;
    int nblk = blockIdx.y;

    extern __shared__ char sm[];
    __shared__ int s_slot[BM];
    int tid = threadIdx.x, lane = tid & 31, wid = tid >> 5;

    int e = 0;
    while (row0 >= g_pbase[e + 1]) e++;
    if (tid < BM) s_slot[tid] = g_perm[row0 + tid];
    __syncthreads();

    size_t wof = ((size_t)e * IN_DIM + (size_t)nblk * 128) * HID;
    const __half* W = g_dn + wof;
    uint32_t sb = smem_u32(sm);

    auto load_stage = [&](int st, int k0) {
        uint32_t base = sb + (uint32_t)st * STG2;
        #pragma unroll
        for (int i = 0; i < 4; i++) {           // A: 128 rows x 8 chunks
            int idx = tid + i * 256;
            int r = idx >> 3, c = idx & 7;
            uint32_t d = base + S2_AH + (uint32_t)(r * LDK + c * 8) * 2;
            size_t ao = (size_t)(row0 + r) * HID + k0 + c * 8;
            cp16(d, g_act + ao, 16);
        }
        #pragma unroll
        for (int i = 0; i < 4; i++) {           // B: 128 rows x 8 chunks
            int idx = tid + i * 256;
            int r = idx >> 3, c = idx & 7;
            uint32_t d = base + S2_BH + (uint32_t)(r * LDK + c * 8) * 2;
            size_t so = (size_t)r * HID + k0 + c * 8;
            cp16(d, W + so, 16);
        }
        cp_commit();
    };

    int wm = (wid >> 1) * 32, wn = (wid & 1) * 64;
    float acc[2][8][4];
    #pragma unroll
    for (int a = 0; a < 2; a++)
        #pragma unroll
        for (int b = 0; b < 8; b++)
            #pragma unroll
            for (int c = 0; c < 4; c++) acc[a][b][c] = 0.f;

    load_stage(0, 0);
    load_stage(1, BK);

    const int NS = HID / BK;  // 32
    for (int s = 0; s < NS; s++) {
        cp_wait1();
        __syncthreads();
        if (s + 2 < NS) load_stage((s + 2) % NSTAGE, (s + 2) * BK);
        else cp_commit();

        uint32_t base = sb + (uint32_t)(s % NSTAGE) * STG2;
        #pragma unroll
        for (int kh = 0; kh < 4; kh++) {
            uint32_t ah[2][4];
            #pragma unroll
            for (int mt = 0; mt < 2; mt++) {
                uint32_t arow = wm + mt * 16 + (lane & 15);
                uint32_t acol = kh * 16 + 8 * (lane >> 4);
                uint32_t off = (arow * LDK + acol) * 2;
                ldm4(ah[mt], base + S2_AH + off);
            }
            uint32_t bh[8][2];
            #pragma unroll
            for (int p = 0; p < 4; p++) {
                uint32_t quad = (uint32_t)(lane >> 3);
                uint32_t brow = wn + p * 16 + (quad >> 1) * 8 + (lane & 7);
                uint32_t bcol = kh * 16 + (quad & 1) * 8;
                uint32_t off = (brow * LDK + bcol) * 2;
                uint32_t t[4];
                ldm4(t, base + S2_BH + off);
                bh[2*p][0]=t[0]; bh[2*p][1]=t[1]; bh[2*p+1][0]=t[2]; bh[2*p+1][1]=t[3];
            }
            #pragma unroll
            for (int mt = 0; mt < 2; mt++)
                #pragma unroll
                for (int nt = 0; nt < 8; nt++) mma16816(acc[mt][nt], ah[mt], bh[nt]);
        }
    }

    #pragma unroll
    for (int mt = 0; mt < 2; mt++) {
        int lr = wm + mt * 16 + (lane >> 2);
        int s0 = s_slot[lr];
        int s1 = s_slot[lr + 8];
        #pragma unroll
        for (int nt = 0; nt < 8; nt++) {
            int gc = nblk * 128 + wn + nt * 8 + (lane & 3) * 2;
            if (s0 >= 0)
                *(float2*)&g_y[(size_t)s0 * IN_DIM + gc] = make_float2(acc[mt][nt][0], acc[mt][nt][1]);
            if (s1 >= 0)
                *(float2*)&g_y[(size_t)s1 * IN_DIM + gc] = make_float2(acc[mt][nt][2], acc[mt][nt][3]);
        }
    }
}

// ---------------- combine ----------------
__global__ void k_combine(const float* __restrict__ wts, float* __restrict__ out) {
    size_t idx4 = ((size_t)blockIdx.x * blockDim.x + threadIdx.x) * 4;
    if (idx4 >= (size_t)SEQ * IN_DIM) return;
    int token = (int)(idx4 / IN_DIM);
    int col = (int)(idx4 % IN_DIM);
    float w0 = wts[token * 2 + 0];
    float w1 = wts[token * 2 + 1];
    float4 y0 = *(const float4*)&g_y[(size_t)(token * 2 + 0) * IN_DIM + col];
    float4 y1 = *(const float4*)&g_y[(size_t)(token * 2 + 1) * IN_DIM + col];
    float4 r;
    r.x = w0 * y0.x + w1 * y1.x;
    r.y = w0 * y0.y + w1 * y1.y;
    r.z = w0 * y0.z + w1 * y1.z;
    r.w = w0 * y0.w + w1 * y1.w;
    *(float4*)&out[idx4] = r;
}

// ---------------- launch ----------------
extern "C" void kernel_launch(void* const* d_in, const int* in_sizes, int n_in,
                              void* d_out, int out_size) {
    const float* inp  = (const float*)d_in[0];
    const float* wts  = (const float*)d_in[1];
    const float* up   = (const float*)d_in[2];
    const float* gate = (const float*)d_in[3];
    const float* down = (const float*)d_in[4];
    const int*   sel  = (const int*)d_in[5];
    float* out = (float*)d_out;

    cudaFuncSetAttribute(k_gemm1, cudaFuncAttributeMaxDynamicSharedMemorySize, SMEM1);
    cudaFuncSetAttribute(k_gemm2, cudaFuncAttributeMaxDynamicSharedMemorySize, SMEM2);

    k_init<<<64, 256>>>();
    k_count<<<NTOK / 256, 256>>>(sel);
    k_scan<<<1, 32>>>();
    k_scatter<<<NTOK / 256, 256>>>(sel);

    k_cvt_w<<<4096, 256>>>(up,   (int)((size_t)NEXP * HID * IN_DIM / 4), 0);
    k_cvt_w<<<4096, 256>>>(gate, (int)((size_t)NEXP * HID * IN_DIM / 4), 1);
    k_cvt_w<<<2048, 256>>>(inp,  SEQ * IN_DIM / 4, 2);
    k_cvt_dnT<<<dim3(IN_DIM / 32, HID / 64, NEXP), dim3(32, 8)>>>(down);

    k_gemm1<<<dim3(PERM_MAX / BM, HID / 64), 256, SMEM1>>>();
    k_gemm2<<<dim3(PERM_MAX / BM, IN_DIM / 128), 256, SMEM2>>>();
    k_combine<<<(SEQ * IN_DIM / 4 + 255) / 256, 256>>>(wts, out);
}

// round 16
// speedup vs baseline: 1.0052x; 1.0052x over previous
#include <cuda_runtime.h>
#include <cuda_fp16.h>
#include <math.h>
#include <stdint.h>

#define SEQ 8192
#define IN_DIM 1024
#define HID 2048
#define NEXP 8
#define TOPK 2
#define NTOK (SEQ * TOPK)
#define BM 128
#define BK 64
#define PERM_MAX (NTOK + NEXP * BM)  // 17408

// smem rows padded to 72 fp16 (144B): 8-row ldmatrix tiles hit disjoint bank groups
#define LDK 72
#define ROW_B (LDK * 2)              // 144 bytes per row

// GEMM1 stage: A(128) U(64) G(64) rows
#define S1_AH 0
#define S1_UH (128 * ROW_B)          // 18432
#define S1_GH (192 * ROW_B)          // 27648
#define STG1  (256 * ROW_B)          // 36864
// GEMM2 stage: A(128) B(128) rows
#define S2_AH 0
#define S2_BH (128 * ROW_B)
#define STG2  (256 * ROW_B)          // 36864
#define NSTAGE 3
#define SMEM1 (NSTAGE * STG1)        // 110592 (x2 CTAs = 221184 < 228KB)
#define SMEM2 (NSTAGE * STG2)        // 110592

// GEMM1 grid partition: first G1_BLKS do GEMM, rest do down-transpose
#define G1_ROWT (PERM_MAX / BM)      // 136
#define G1_NBLK (HID / 64)           // 32
#define G1_BLKS (G1_ROWT * G1_NBLK)  // 4352
#define DNT_BLKS (32 * (HID / 64) * NEXP)  // 32 n-tiles x 32 k-tiles x 8 = 8192

// ---------------- static device scratch ----------------
__device__ int g_count[NEXP];
__device__ int g_fill[NEXP];
__device__ int g_pbase[NEXP + 1];
__device__ int g_perm[PERM_MAX];

__device__ __half g_up[(size_t)NEXP * HID * IN_DIM];
__device__ __half g_gt[(size_t)NEXP * HID * IN_DIM];
__device__ __half g_dn[(size_t)NEXP * IN_DIM * HID];   // transposed [e][n][k]
__device__ __half g_in[(size_t)SEQ * IN_DIM];
__device__ __half g_act[(size_t)PERM_MAX * HID];
__device__ float g_y[(size_t)NTOK * IN_DIM];

// ---------------- helpers ----------------
__device__ __forceinline__ uint32_t smem_u32(const void* p) {
    uint32_t a;
    asm("{ .reg .u64 t; cvta.to.shared.u64 t, %1; cvt.u32.u64 %0, t; }" : "=r"(a) : "l"(p));
    return a;
}
__device__ __forceinline__ void cp16(uint32_t dst, const void* src, int sz) {
    asm volatile("cp.async.cg.shared.global [%0], [%1], 16, %2;" :: "r"(dst), "l"(src), "r"(sz) : "memory");
}
__device__ __forceinline__ void cp_commit() { asm volatile("cp.async.commit_group;" ::: "memory"); }
__device__ __forceinline__ void cp_wait1() { asm volatile("cp.async.wait_group 1;" ::: "memory"); }

__device__ __forceinline__ void ldm4(uint32_t* r, uint32_t a) {
    asm volatile("ldmatrix.sync.aligned.m8n8.x4.shared.b16 {%0,%1,%2,%3},[%4];"
                 : "=r"(r[0]), "=r"(r[1]), "=r"(r[2]), "=r"(r[3]) : "r"(a));
}
__device__ __forceinline__ void mma16816(float* c, const uint32_t* a, const uint32_t* b) {
    asm volatile("mma.sync.aligned.m16n8k16.row.col.f32.f16.f16.f32 "
                 "{%0,%1,%2,%3},{%4,%5,%6,%7},{%8,%9},{%0,%1,%2,%3};"
                 : "+f"(c[0]), "+f"(c[1]), "+f"(c[2]), "+f"(c[3])
                 : "r"(a[0]), "r"(a[1]), "r"(a[2]), "r"(a[3]), "r"(b[0]), "r"(b[1]));
}
__device__ __forceinline__ float fast_tanh(float x) {
    float y;
    asm("tanh.approx.f32 %0, %1;" : "=f"(y) : "f"(x));
    return y;
}
__device__ __forceinline__ float gelu_tanh(float x) {
    float x3 = x * x * x;
    return 0.5f * x * (1.f + fast_tanh(0.7978845608028654f * (x + 0.044715f * x3)));
}

// ---------------- routing ----------------
__global__ void k_init() {
    int i = blockIdx.x * blockDim.x + threadIdx.x;
    if (i < NEXP) { g_count[i] = 0; g_fill[i] = 0; }
    for (int j = i; j < PERM_MAX; j += gridDim.x * blockDim.x) g_perm[j] = -1;
}
__global__ void k_count(const int* __restrict__ sel) {
    int s = blockIdx.x * blockDim.x + threadIdx.x;
    if (s < NTOK) atomicAdd(&g_count[sel[s]], 1);
}
__global__ void k_scan() {
    if (threadIdx.x == 0) {
        int acc = 0;
        g_pbase[0] = 0;
        for (int e = 0; e < NEXP; e++) {
            acc += ((g_count[e] + BM - 1) / BM) * BM;
            g_pbase[e + 1] = acc;
        }
    }
}
__global__ void k_scatter(const int* __restrict__ sel) {
    int s = blockIdx.x * blockDim.x + threadIdx.x;
    if (s < NTOK) {
        int e = sel[s];
        int pos = g_pbase[e] + atomicAdd(&g_fill[e], 1);
        g_perm[pos] = s;
    }
}

// ---------------- conversions ----------------
__global__ void k_cvt_w(const float* __restrict__ src, int n4, int which) {
    __half* dst = (which == 0) ? g_up : ((which == 1) ? g_gt : g_in);
    for (int i = blockIdx.x * blockDim.x + threadIdx.x; i < n4; i += gridDim.x * blockDim.x) {
        float4 v = ((const float4*)src)[i];
        __half2* D = (__half2*)dst + 2 * (size_t)i;
        D[0] = __halves2half2(__float2half_rn(v.x), __float2half_rn(v.y));
        D[1] = __halves2half2(__float2half_rn(v.z), __float2half_rn(v.w));
    }
}

// ---------------- GEMM1 fused (BM=128, BN=64, BK=64, occ 2) + folded down-transpose ----------------
// blocks [0, G1_BLKS): GEMM1 with epilogue gelu*h -> act fp16
// blocks [G1_BLKS, G1_BLKS+DNT_BLKS): down [e][k][n] -> g_dn [e][n][k] (needed only by GEMM2)
__global__ __launch_bounds__(256, 2) void k_gemm1(const float* __restrict__ down) {
    extern __shared__ char sm[];
    int tid = threadIdx.x;

    if (blockIdx.x >= G1_BLKS) {
        // ---- folded transpose block: 32 n-cols x 64 k-rows ----
        float (*t)[65] = (float(*)[65])sm;
        int b = blockIdx.x - G1_BLKS;
        int tx = tid & 31, ty = tid >> 5;      // 32 x 8
        int n0 = (b & 31) * 32;
        int k0 = ((b >> 5) & 31) * 64;
        int e  = b >> 10;
        #pragma unroll
        for (int kr = ty; kr < 64; kr += 8)
            t[tx][kr] = down[((size_t)e * HID + k0 + kr) * IN_DIM + n0 + tx];
        __syncthreads();
        #pragma unroll
        for (int nr = ty; nr < 32; nr += 8) {
            float a = t[nr][2 * tx], bV = t[nr][2 * tx + 1];
            __half2 h = __halves2half2(__float2half_rn(a), __float2half_rn(bV));
            *(__half2*)&g_dn[((size_t)e * IN_DIM + n0 + nr) * HID + k0 + 2 * tx] = h;
        }
        return;
    }

    int rowt = blockIdx.x % G1_ROWT;
    int nblk = blockIdx.x / G1_ROWT;
    int row0 = rowt * BM;
    if (row0 >= g_pbase[NEXP]) return;

    __shared__ int s_tok[BM];
    int lane = tid & 31, wid = tid >> 5;

    int e = 0;
    while (row0 >= g_pbase[e + 1]) e++;
    if (tid < BM) {
        int s = g_perm[row0 + tid];
        s_tok[tid] = (s >= 0) ? (s >> 1) : -1;
    }
    __syncthreads();

    size_t wof = ((size_t)e * HID + (size_t)nblk * 64) * IN_DIM;
    const __half* U = g_up + wof;
    const __half* G = g_gt + wof;
    uint32_t sb = smem_u32(sm);

    auto load_stage = [&](int st, int k0) {
        uint32_t base = sb + (uint32_t)st * STG1;
        #pragma unroll
        for (int i = 0; i < 4; i++) {           // A: 128 rows x 8 chunks = 1024 cp
            int idx = tid + i * 256;
            int r = idx >> 3, c = idx & 7;
            uint32_t d = base + S1_AH + (uint32_t)(r * LDK + c * 8) * 2;
            int tok = s_tok[r];
            size_t ao = (size_t)(tok < 0 ? 0 : tok) * IN_DIM + k0 + c * 8;
            cp16(d, g_in + ao, tok < 0 ? 0 : 16);
        }
        #pragma unroll
        for (int i = 0; i < 4; i++) {           // U/G: 64 rows x 8 chunks x 2 = 1024 cp
            int idx = tid + i * 256;
            int r = idx >> 4, wsel = (idx >> 3) & 1, c = idx & 7;
            uint32_t d = base + (wsel ? S1_GH : S1_UH) + (uint32_t)(r * LDK + c * 8) * 2;
            size_t so = (size_t)r * IN_DIM + k0 + c * 8;
            cp16(d, (wsel ? G : U) + so, 16);
        }
        cp_commit();
    };

    int wm = (wid >> 1) * 32, wn = (wid & 1) * 32;
    float acc_u[2][4][4], acc_g[2][4][4];
    #pragma unroll
    for (int a = 0; a < 2; a++)
        #pragma unroll
        for (int b = 0; b < 4; b++)
            #pragma unroll
            for (int c = 0; c < 4; c++) { acc_u[a][b][c] = 0.f; acc_g[a][b][c] = 0.f; }

    load_stage(0, 0);
    load_stage(1, BK);

    const int NS = IN_DIM / BK;  // 16
    for (int s = 0; s < NS; s++) {
        cp_wait1();
        __syncthreads();
        if (s + 2 < NS) load_stage((s + 2) % NSTAGE, (s + 2) * BK);
        else cp_commit();

        uint32_t base = sb + (uint32_t)(s % NSTAGE) * STG1;
        #pragma unroll
        for (int kh = 0; kh < 4; kh++) {
            uint32_t ah[2][4];
            #pragma unroll
            for (int mt = 0; mt < 2; mt++) {
                uint32_t arow = wm + mt * 16 + (lane & 15);
                uint32_t acol = kh * 16 + 8 * (lane >> 4);
                uint32_t off = (arow * LDK + acol) * 2;
                ldm4(ah[mt], base + S1_AH + off);
            }
            uint32_t ub[4][2], gb[4][2];
            #pragma unroll
            for (int p = 0; p < 2; p++) {
                uint32_t quad = (uint32_t)(lane >> 3);
                uint32_t brow = wn + p * 16 + (quad >> 1) * 8 + (lane & 7);
                uint32_t bcol = kh * 16 + (quad & 1) * 8;
                uint32_t off = (brow * LDK + bcol) * 2;
                uint32_t t[4];
                ldm4(t, base + S1_UH + off);
                ub[2*p][0]=t[0]; ub[2*p][1]=t[1]; ub[2*p+1][0]=t[2]; ub[2*p+1][1]=t[3];
                ldm4(t, base + S1_GH + off);
                gb[2*p][0]=t[0]; gb[2*p][1]=t[1]; gb[2*p+1][0]=t[2]; gb[2*p+1][1]=t[3];
            }
            #pragma unroll
            for (int mt = 0; mt < 2; mt++)
                #pragma unroll
                for (int nt = 0; nt < 4; nt++) mma16816(acc_u[mt][nt], ah[mt], ub[nt]);
            #pragma unroll
            for (int mt = 0; mt < 2; mt++)
                #pragma unroll
                for (int nt = 0; nt < 4; nt++) mma16816(acc_g[mt][nt], ah[mt], gb[nt]);
        }
    }

    // epilogue: act = gelu(g) * h -> fp16
    #pragma unroll
    for (int mt = 0; mt < 2; mt++) {
        int gr = row0 + wm + mt * 16 + (lane >> 2);
        #pragma unroll
        for (int nt = 0; nt < 4; nt++) {
            int gc = nblk * 64 + wn + nt * 8 + (lane & 3) * 2;
            #pragma unroll
            for (int half = 0; half < 2; half++) {
                float a0 = gelu_tanh(acc_g[mt][nt][2 * half])     * acc_u[mt][nt][2 * half];
                float a1 = gelu_tanh(acc_g[mt][nt][2 * half + 1]) * acc_u[mt][nt][2 * half + 1];
                __half2 hp = __halves2half2(__float2half_rn(a0), __float2half_rn(a1));
                size_t o = (size_t)(gr + 8 * half) * HID + gc;
                *(uint32_t*)&g_act[o] = *(uint32_t*)&hp;
            }
        }
    }
}

// ---------------- GEMM2 (BM=128, BN=128, BK=64, occ 2): act @ downT ----------------
__global__ __launch_bounds__(256, 2) void k_gemm2() {
    int row0 = blockIdx.x * BM;
    if (row0 >= g_pbase[NEXP]) return;
    int nblk = blockIdx.y;

    extern __shared__ char sm[];
    __shared__ int s_slot[BM];
    int tid = threadIdx.x, lane = tid & 31, wid = tid >> 5;

    int e = 0;
    while (row0 >= g_pbase[e + 1]) e++;
    if (tid < BM) s_slot[tid] = g_perm[row0 + tid];
    __syncthreads();

    size_t wof = ((size_t)e * IN_DIM + (size_t)nblk * 128) * HID;
    const __half* W = g_dn + wof;
    uint32_t sb = smem_u32(sm);

    auto load_stage = [&](int st, int k0) {
        uint32_t base = sb + (uint32_t)st * STG2;
        #pragma unroll
        for (int i = 0; i < 4; i++) {           // A: 128 rows x 8 chunks
            int idx = tid + i * 256;
            int r = idx >> 3, c = idx & 7;
            uint32_t d = base + S2_AH + (uint32_t)(r * LDK + c * 8) * 2;
            size_t ao = (size_t)(row0 + r) * HID + k0 + c * 8;
            cp16(d, g_act + ao, 16);
        }
        #pragma unroll
        for (int i = 0; i < 4; i++) {           // B: 128 rows x 8 chunks
            int idx = tid + i * 256;
            int r = idx >> 3, c = idx & 7;
            uint32_t d = base + S2_BH + (uint32_t)(r * LDK + c * 8) * 2;
            size_t so = (size_t)r * HID + k0 + c * 8;
            cp16(d, W + so, 16);
        }
        cp_commit();
    };

    int wm = (wid >> 1) * 32, wn = (wid & 1) * 64;
    float acc[2][8][4];
    #pragma unroll
    for (int a = 0; a < 2; a++)
        #pragma unroll
        for (int b = 0; b < 8; b++)
            #pragma unroll
            for (int c = 0; c < 4; c++) acc[a][b][c] = 0.f;

    load_stage(0, 0);
    load_stage(1, BK);

    const int NS = HID / BK;  // 32
    for (int s = 0; s < NS; s++) {
        cp_wait1();
        __syncthreads();
        if (s + 2 < NS) load_stage((s + 2) % NSTAGE, (s + 2) * BK);
        else cp_commit();

        uint32_t base = sb + (uint32_t)(s % NSTAGE) * STG2;
        #pragma unroll
        for (int kh = 0; kh < 4; kh++) {
            uint32_t ah[2][4];
            #pragma unroll
            for (int mt = 0; mt < 2; mt++) {
                uint32_t arow = wm + mt * 16 + (lane & 15);
                uint32_t acol = kh * 16 + 8 * (lane >> 4);
                uint32_t off = (arow * LDK + acol) * 2;
                ldm4(ah[mt], base + S2_AH + off);
            }
            uint32_t bh[8][2];
            #pragma unroll
            for (int p = 0; p < 4; p++) {
                uint32_t quad = (uint32_t)(lane >> 3);
                uint32_t brow = wn + p * 16 + (quad >> 1) * 8 + (lane & 7);
                uint32_t bcol = kh * 16 + (quad & 1) * 8;
                uint32_t off = (brow * LDK + bcol) * 2;
                uint32_t t[4];
                ldm4(t, base + S2_BH + off);
                bh[2*p][0]=t[0]; bh[2*p][1]=t[1]; bh[2*p+1][0]=t[2]; bh[2*p+1][1]=t[3];
            }
            #pragma unroll
            for (int mt = 0; mt < 2; mt++)
                #pragma unroll
                for (int nt = 0; nt < 8; nt++) mma16816(acc[mt][nt], ah[mt], bh[nt]);
        }
    }

    #pragma unroll
    for (int mt = 0; mt < 2; mt++) {
        int lr = wm + mt * 16 + (lane >> 2);
        int s0 = s_slot[lr];
        int s1 = s_slot[lr + 8];
        #pragma unroll
        for (int nt = 0; nt < 8; nt++) {
            int gc = nblk * 128 + wn + nt * 8 + (lane & 3) * 2;
            if (s0 >= 0)
                *(float2*)&g_y[(size_t)s0 * IN_DIM + gc] = make_float2(acc[mt][nt][0], acc[mt][nt][1]);
            if (s1 >= 0)
                *(float2*)&g_y[(size_t)s1 * IN_DIM + gc] = make_float2(acc[mt][nt][2], acc[mt][nt][3]);
        }
    }
}

// ---------------- combine ----------------
__global__ void k_combine(const float* __restrict__ wts, float* __restrict__ out) {
    size_t idx4 = ((size_t)blockIdx.x * blockDim.x + threadIdx.x) * 4;
    if (idx4 >= (size_t)SEQ * IN_DIM) return;
    int token = (int)(idx4 / IN_DIM);
    int col = (int)(idx4 % IN_DIM);
    float w0 = wts[token * 2 + 0];
    float w1 = wts[token * 2 + 1];
    float4 y0 = *(const float4*)&g_y[(size_t)(token * 2 + 0) * IN_DIM + col];
    float4 y1 = *(const float4*)&g_y[(size_t)(token * 2 + 1) * IN_DIM + col];
    float4 r;
    r.x = w0 * y0.x + w1 * y1.x;
    r.y = w0 * y0.y + w1 * y1.y;
    r.z = w0 * y0.z + w1 * y1.z;
    r.w = w0 * y0.w + w1 * y1.w;
    *(float4*)&out[idx4] = r;
}

// ---------------- launch ----------------
extern "C" void kernel_launch(void* const* d_in, const int* in_sizes, int n_in,
                              void* d_out, int out_size) {
    const float* inp  = (const float*)d_in[0];
    const float* wts  = (const float*)d_in[1];
    const float* up   = (const float*)d_in[2];
    const float* gate = (const float*)d_in[3];
    const float* down = (const float*)d_in[4];
    const int*   sel  = (const int*)d_in[5];
    float* out = (float*)d_out;

    cudaFuncSetAttribute(k_gemm1, cudaFuncAttributeMaxDynamicSharedMemorySize, SMEM1);
    cudaFuncSetAttribute(k_gemm2, cudaFuncAttributeMaxDynamicSharedMemorySize, SMEM2);

    k_init<<<64, 256>>>();
    k_count<<<NTOK / 256, 256>>>(sel);
    k_scan<<<1, 32>>>();
    k_scatter<<<NTOK / 256, 256>>>(sel);

    k_cvt_w<<<4096, 256>>>(up,   (int)((size_t)NEXP * HID * IN_DIM / 4), 0);
    k_cvt_w<<<4096, 256>>>(gate, (int)((size_t)NEXP * HID * IN_DIM / 4), 1);
    k_cvt_w<<<2048, 256>>>(inp,  SEQ * IN_DIM / 4, 2);

    k_gemm1<<<G1_BLKS + DNT_BLKS, 256, SMEM1>>>(down);  // GEMM1 + folded down-transpose
    k_gemm2<<<dim3(PERM_MAX / BM, IN_DIM / 128), 256, SMEM2>>>();
    k_combine<<<(SEQ * IN_DIM / 4 + 255) / 256, 256>>>(wts, out);
}